// round 9
// baseline (speedup 1.0000x reference)
#include <cuda_runtime.h>
#include <cuda_bf16.h>
#include <cstdint>
#include <math.h>

// Problem constants
constexpr int B  = 8;
constexpr int L  = 2048;
constexpr int H  = 256;
constexpr int BL = B * L;
constexpr float L2E = 1.4426950408889634f;
constexpr int PAD = 40;   // halfs per smem row in k_proj (80B) -> conflict-free

// Scratch (device globals; no allocation allowed)
__device__ float g_st[BL];              // tanh(text@Wt^T+bt)@wa[:H]
__device__ float g_so[BL];              // tanh(opinion@Wo^T)@wa[H:]
__device__ float g_mx[BL];              // row max of L2E-scaled scores
__device__ signed char g_V8h[B * H * L];  // V^T int8 hi: round(v*16)
__device__ signed char g_V8l[B * H * L];  // V^T int8 lo: round((v*16-hi)*128)

// ---- helpers ----
__device__ __forceinline__ void bf16_split(float x, unsigned short& h,
                                           unsigned short& l) {
    __nv_bfloat16 hb = __float2bfloat16(x);
    float hf = __bfloat162float(hb);
    __nv_bfloat16 lb = __float2bfloat16(x - hf);
    h = __bfloat16_as_ushort(hb);
    l = __bfloat16_as_ushort(lb);
}
__device__ __forceinline__ uint32_t pack2(unsigned short lo, unsigned short hi) {
    return (uint32_t)lo | ((uint32_t)hi << 16);
}
__device__ __forceinline__ float ex2(float x) {
    float r;
    asm("ex2.approx.f32 %0, %1;" : "=f"(r) : "f"(x));
    return r;
}
__device__ __forceinline__ uint32_t smem_u32(const void* p) {
    uint32_t a;
    asm("{ .reg .u64 t; cvta.to.shared.u64 t, %1; cvt.u32.u64 %0, t; }"
        : "=r"(a) : "l"(p));
    return a;
}

// ---- warp MMAs ----
__device__ __forceinline__ void mma_bf16(float* c, const uint32_t* a,
                                         uint32_t b0, uint32_t b1) {
    asm volatile(
        "mma.sync.aligned.m16n8k16.row.col.f32.bf16.bf16.f32 "
        "{%0,%1,%2,%3}, {%4,%5,%6,%7}, {%8,%9}, {%0,%1,%2,%3};"
        : "+f"(c[0]), "+f"(c[1]), "+f"(c[2]), "+f"(c[3])
        : "r"(a[0]), "r"(a[1]), "r"(a[2]), "r"(a[3]), "r"(b0), "r"(b1));
}
__device__ __forceinline__ void imma_u8s8(int* c, const uint32_t* a,
                                          const uint32_t* b) {
    asm volatile(
        "mma.sync.aligned.m16n8k32.row.col.s32.u8.s8.s32 "
        "{%0,%1,%2,%3}, {%4,%5,%6,%7}, {%8,%9}, {%0,%1,%2,%3};"
        : "+r"(c[0]), "+r"(c[1]), "+r"(c[2]), "+r"(c[3])
        : "r"(a[0]), "r"(a[1]), "r"(a[2]), "r"(a[3]), "r"(b[0]), "r"(b[1]));
}
__device__ __forceinline__ void imma_s8s8(int* c, const uint32_t* a,
                                          const uint32_t* b) {
    asm volatile(
        "mma.sync.aligned.m16n8k32.row.col.s32.s8.s8.s32 "
        "{%0,%1,%2,%3}, {%4,%5,%6,%7}, {%8,%9}, {%0,%1,%2,%3};"
        : "+r"(c[0]), "+r"(c[1]), "+r"(c[2]), "+r"(c[3])
        : "r"(a[0]), "r"(a[1]), "r"(a[2]), "r"(a[3]), "r"(b[0]), "r"(b[1]));
}
__device__ __forceinline__ void ldsm_x4(uint32_t* r, uint32_t addr) {
    asm volatile("ldmatrix.sync.aligned.m8n8.x4.shared.b16 {%0,%1,%2,%3}, [%4];"
                 : "=r"(r[0]), "=r"(r[1]), "=r"(r[2]), "=r"(r[3])
                 : "r"(addr));
}
__device__ __forceinline__ void ldsm_x2(uint32_t* r, uint32_t addr) {
    asm volatile("ldmatrix.sync.aligned.m8n8.x2.shared.b16 {%0,%1}, [%2];"
                 : "=r"(r[0]), "=r"(r[1]) : "r"(addr));
}

// ---------------------------------------------------------------------------
// Kernel VT: transpose + int8 2-term split: opin -> g_V8h/g_V8l [b][h][j]
// ---------------------------------------------------------------------------
__global__ __launch_bounds__(256)
void k_vt(const float* __restrict__ opin) {
    __shared__ float tile[64][33];
    const int b = blockIdx.z;
    const int j0 = blockIdx.x * 64;
    const int h0 = blockIdx.y * 32;
    const int tid = threadIdx.x;

#pragma unroll
    for (int it = tid; it < 512; it += 256) {
        int j = it >> 3, hq = (it & 7) * 4;
        float4 v = *(const float4*)&opin[((size_t)(b * L + j0 + j)) * H + h0 + hq];
        tile[j][hq + 0] = v.x; tile[j][hq + 1] = v.y;
        tile[j][hq + 2] = v.z; tile[j][hq + 3] = v.w;
    }
    __syncthreads();

    const int h = tid >> 3, jq = (tid & 7) * 8;
    uint32_t uh[2] = {0, 0}, ul[2] = {0, 0};
#pragma unroll
    for (int k = 0; k < 8; k++) {
        float v = tile[jq + k][h];
        v = fminf(fmaxf(v, -7.9f), 7.9f);
        float vs = v * 16.0f;
        int vh = __float2int_rn(vs);
        float r = vs - (float)vh;
        int vl = __float2int_rn(r * 128.0f);
        uh[k >> 2] |= ((uint32_t)vh & 0xFF) << (8 * (k & 3));
        ul[k >> 2] |= ((uint32_t)vl & 0xFF) << (8 * (k & 3));
    }
    const size_t o = ((size_t)(b * H + h0 + h)) * L + j0 + jq;
    *(uint2*)&g_V8h[o] = make_uint2(uh[0], uh[1]);
    *(uint2*)&g_V8l[o] = make_uint2(ul[0], ul[1]);
}

// ---------------------------------------------------------------------------
// Kernel 1: st / so projections via bf16 tensor cores (unchanged, 3-term).
// ---------------------------------------------------------------------------
constexpr uint32_t PROJ_SMEM = (2 * 64 * PAD + 2 * 256 * PAD) * 2 + 64 * 4;

__global__ __launch_bounds__(256, 2)
void k_proj(const float* __restrict__ text, const float* __restrict__ opin,
            const float* __restrict__ Wt, const float* __restrict__ bt,
            const float* __restrict__ Wo, const float* __restrict__ wa) {
    extern __shared__ char smraw[];
    unsigned short* Xh = (unsigned short*)smraw;
    unsigned short* Xl = Xh + 64 * PAD;
    unsigned short* Wh = Xl + 64 * PAD;
    unsigned short* Wl = Wh + 256 * PAD;
    float* stp = (float*)(Wl + 256 * PAD);

    const bool isT = (blockIdx.y == 0);
    const float* X = isT ? text : opin;
    const float* W = isT ? Wt : Wo;
    const int row0 = blockIdx.x * 64;
    const int tid = threadIdx.x;
    const int warp = tid >> 5, lane = tid & 31;
    const int wm = warp & 1, wn = warp >> 1;
    const int g = lane >> 2, c4 = lane & 3;

    float acc[2][8][4];
#pragma unroll
    for (int mt = 0; mt < 2; mt++)
#pragma unroll
        for (int nt = 0; nt < 8; nt++)
#pragma unroll
            for (int e = 0; e < 4; e++) acc[mt][nt][e] = 0.0f;

    const int xi = tid >> 2, xk = (tid & 3) * 8;

    for (int kt = 0; kt < 8; kt++) {
        const int k0 = kt * 32;
        float4 xv0 = *(const float4*)&X[(size_t)(row0 + xi) * H + k0 + xk];
        float4 xv1 = *(const float4*)&X[(size_t)(row0 + xi) * H + k0 + xk + 4];
        float4 wv[8];
#pragma unroll
        for (int q = 0; q < 8; q++)
            wv[q] = *(const float4*)&W[(size_t)tid * H + k0 + 4 * q];

        __syncthreads();
        {
            float xf[8] = {xv0.x, xv0.y, xv0.z, xv0.w, xv1.x, xv1.y, xv1.z, xv1.w};
#pragma unroll
            for (int q = 0; q < 8; q += 2) {
                unsigned short h0s, l0s, h1s, l1s;
                bf16_split(xf[q], h0s, l0s);
                bf16_split(xf[q + 1], h1s, l1s);
                *(uint32_t*)&Xh[xi * PAD + xk + q] = pack2(h0s, h1s);
                *(uint32_t*)&Xl[xi * PAD + xk + q] = pack2(l0s, l1s);
            }
        }
#pragma unroll
        for (int q = 0; q < 8; q++) {
            float wf[4] = {wv[q].x, wv[q].y, wv[q].z, wv[q].w};
#pragma unroll
            for (int e = 0; e < 4; e += 2) {
                unsigned short h0s, l0s, h1s, l1s;
                bf16_split(wf[e], h0s, l0s);
                bf16_split(wf[e + 1], h1s, l1s);
                *(uint32_t*)&Wh[tid * PAD + 4 * q + e] = pack2(h0s, h1s);
                *(uint32_t*)&Wl[tid * PAD + 4 * q + e] = pack2(l0s, l1s);
            }
        }
        __syncthreads();

#pragma unroll
        for (int ks = 0; ks < 2; ks++) {
            const int kb = ks * 16;
            uint32_t aH[2][4], aL[2][4];
#pragma unroll
            for (int mt = 0; mt < 2; mt++) {
                int base = (wm * 32 + mt * 16 + g) * PAD + kb + 2 * c4;
                aH[mt][0] = *(uint32_t*)&Xh[base];
                aH[mt][1] = *(uint32_t*)&Xh[base + 8 * PAD];
                aH[mt][2] = *(uint32_t*)&Xh[base + 8];
                aH[mt][3] = *(uint32_t*)&Xh[base + 8 * PAD + 8];
                aL[mt][0] = *(uint32_t*)&Xl[base];
                aL[mt][1] = *(uint32_t*)&Xl[base + 8 * PAD];
                aL[mt][2] = *(uint32_t*)&Xl[base + 8];
                aL[mt][3] = *(uint32_t*)&Xl[base + 8 * PAD + 8];
            }
#pragma unroll
            for (int nt = 0; nt < 8; nt++) {
                int bb = (wn * 64 + nt * 8 + g) * PAD + kb + 2 * c4;
                uint32_t bH0 = *(uint32_t*)&Wh[bb], bH1 = *(uint32_t*)&Wh[bb + 8];
                uint32_t bL0 = *(uint32_t*)&Wl[bb], bL1 = *(uint32_t*)&Wl[bb + 8];
#pragma unroll
                for (int mt = 0; mt < 2; mt++) {
                    mma_bf16(acc[mt][nt], aH[mt], bH0, bH1);
                    mma_bf16(acc[mt][nt], aH[mt], bL0, bL1);
                    mma_bf16(acc[mt][nt], aL[mt], bH0, bH1);
                }
            }
        }
    }

    if (tid < 64) stp[tid] = 0.0f;
    __syncthreads();
    const int wo = isT ? 0 : H;
#pragma unroll
    for (int mt = 0; mt < 2; mt++) {
#pragma unroll
        for (int hr = 0; hr < 2; hr++) {
            float s = 0.0f;
#pragma unroll
            for (int nt = 0; nt < 8; nt++) {
#pragma unroll
                for (int e = 0; e < 2; e++) {
                    int col = wn * 64 + nt * 8 + 2 * c4 + e;
                    float tv = acc[mt][nt][hr * 2 + e];
                    if (isT) tv += bt[col];
                    s += tanhf(tv) * wa[wo + col];
                }
            }
            s += __shfl_xor_sync(0xffffffffu, s, 1);
            s += __shfl_xor_sync(0xffffffffu, s, 2);
            if (c4 == 0)
                atomicAdd(&stp[wm * 32 + mt * 16 + hr * 8 + g], s);
        }
    }
    __syncthreads();
    if (tid < 64) {
        float* dst = isT ? g_st : g_so;
        dst[row0 + tid] = stp[tid];
    }
}

// ---------------------------------------------------------------------------
// Kernel 2: exact per-row max of L2E-scaled scores. MUST use identical fp
// arithmetic to k_pv's producer so p = exp2(s - mx) <= 1 exactly.
// CTA: 64 rows, 4 threads/row x 512 j each.
// ---------------------------------------------------------------------------
__global__ __launch_bounds__(256)
void k_max(const int* __restrict__ pos, const float* __restrict__ ba) {
    __shared__ float2 msm[L];
    __shared__ float rlut[L];
    const int b = blockIdx.x >> 5;
    const int i0 = (blockIdx.x & 31) * 64;
    const int tid = threadIdx.x;

    for (int j = tid; j < L; j += 256) {
        int p = pos[b * L + j];
        bool op = (p >= 19 && p <= 21) || (p >= 33 && p <= 35) ||
                  (p >= 41 && p <= 46);
        float mu = op ? 8.0f : 1.0f;
        msm[j] = make_float2(mu, g_so[b * L + j] * mu);
    }
    for (int d = tid; d < L; d += 256)
        rlut[d] = ((d == 0) ? 0.5f : 1.0f / log2f(2.0f + (float)d)) * L2E;
    __syncthreads();

    const int ri = tid >> 2, seg = tid & 3;
    const int gi = i0 + ri;
    const float sti = g_st[b * L + gi] + ba[0];

    float m = -1e30f;
    for (int jj = 0; jj < 512; jj++) {
        int j = seg * 512 + jj;
        float2 mm = msm[j];
        float s = fmaf(sti, mm.x, mm.y) * rlut[abs(gi - j)];
        m = fmaxf(m, s);
    }
    m = fmaxf(m, __shfl_xor_sync(0xffffffffu, m, 1));
    m = fmaxf(m, __shfl_xor_sync(0xffffffffu, m, 2));
    if (seg == 0) g_mx[b * L + gi] = m;
}

// ---------------------------------------------------------------------------
// Kernel 3: PV via int8 IMMA m16n8k32 (3 fixed-point terms, 2 s32 acc sets).
// p = exp2(s - mx) in [0,1]: p ~ Ph/255 + Pl/(255*128)   (u8 + s8)
// v ~ Vh/16 + Vl/2048                                    (s8 + s8)
// D = [PhVh]*c1 + [PhVl + PlVh]*c1/128; row-normalized by fp32 l (by-product).
// CTA: 64 i x 128 h, 8 warps (2m x 4n, warp 32x32), j-chunks of 32,
// double-buffered, ldmatrix over 16B segments with 48B row stride.
// ---------------------------------------------------------------------------
constexpr uint32_t STR    = 48;               // smem row stride (bytes)
constexpr uint32_t OFF_PH = 0;                // 64*48   = 3072 (u8)
constexpr uint32_t OFF_PL = 3072;             // 3072 (s8)
constexpr uint32_t OFF_VH = 6144;             // 128*48  = 6144 (s8)
constexpr uint32_t OFF_VL = 12288;            // 6144 (s8)
constexpr uint32_t BUF    = 18432;
constexpr uint32_t OFF_MSM  = 2 * BUF;        // 36864: float2[2048]
constexpr uint32_t OFF_RLUT = OFF_MSM + 16384;  // 53248: float[2048]
constexpr uint32_t OFF_STI  = OFF_RLUT + 8192;  // 61440: float[64]
constexpr uint32_t OFF_MX   = OFF_STI + 256;    // 61696: float[64]
constexpr uint32_t OFF_LS   = OFF_MX + 256;     // 61952: float[64]
constexpr uint32_t OFF_LINV = OFF_LS + 256;     // 62208: float[64]
constexpr uint32_t PV_SMEM  = OFF_LINV + 256;   // 62464

__global__ __launch_bounds__(256, 2)
void k_pv(const int* __restrict__ pos, const float* __restrict__ ba,
          float* __restrict__ out) {
    extern __shared__ char smc[];
    const uint32_t sb = smem_u32(smc);

    float2* msm  = (float2*)(smc + OFF_MSM);
    float*  rlut = (float*)(smc + OFF_RLUT);
    float*  stis = (float*)(smc + OFF_STI);
    float*  mxs  = (float*)(smc + OFF_MX);
    float*  ls   = (float*)(smc + OFF_LS);
    float*  linv = (float*)(smc + OFF_LINV);

    const int cta = blockIdx.x;
    const int b = cta >> 6;                 // 64 CTAs per batch
    const int i0 = ((cta >> 1) & 31) * 64;
    const int h0 = (cta & 1) * 128;
    const int tid = threadIdx.x;
    const int warp = tid >> 5, lane = tid & 31;
    const int wm = warp >> 2, wn = warp & 3;   // 2m x 4n, warp tile 32x32

    // prologue tables
    for (int j = tid; j < L; j += 256) {
        int p = pos[b * L + j];
        bool op = (p >= 19 && p <= 21) || (p >= 33 && p <= 35) ||
                  (p >= 41 && p <= 46);
        float mu = op ? 8.0f : 1.0f;
        msm[j] = make_float2(mu, g_so[b * L + j] * mu);
    }
    for (int d = tid; d < L; d += 256)
        rlut[d] = ((d == 0) ? 0.5f : 1.0f / log2f(2.0f + (float)d)) * L2E;
    if (tid < 64) {
        stis[tid] = g_st[b * L + i0 + tid] + ba[0];
        mxs[tid]  = g_mx[b * L + i0 + tid];
    }
    __syncthreads();

    // producer maps
    const int pi = tid >> 2, pq = (tid & 3) * 8;   // P: row pi, 8 j's
    const int gi = i0 + pi;
    const float sti = stis[pi];
    const float mx = mxs[pi];
    const int vrow = tid >> 1, vs = (tid & 1) * 16;  // V: row vrow, 16 bytes
    const signed char* vhp = &g_V8h[(size_t)(b * H + h0 + vrow) * L + vs];
    const signed char* vlp = &g_V8l[(size_t)(b * H + h0 + vrow) * L + vs];
    float lsum = 0.0f;

    // ldmatrix lane offsets (bytes)
    const uint32_t aoff = (wm * 32 + (lane & 7) + 8 * ((lane >> 3) & 1)) * STR +
                          (lane >> 4) * 16;
    const uint32_t boff = (wn * 32 + (lane & 7)) * STR + ((lane >> 3) & 1) * 16;

    int S1[2][4][4], S23[2][4][4];
#pragma unroll
    for (int mt = 0; mt < 2; mt++)
#pragma unroll
        for (int nt = 0; nt < 4; nt++)
#pragma unroll
            for (int e = 0; e < 4; e++) { S1[mt][nt][e] = 0; S23[mt][nt][e] = 0; }

    auto produce = [&](int ct) {
        char* bufc = smc + (ct & 1) * BUF;
        const int j0 = ct * 32;
        // V copy (global int8 planes -> padded smem)
        uint4 vh = *(const uint4*)(vhp + j0);
        uint4 vl = *(const uint4*)(vlp + j0);
        *(uint4*)(bufc + OFF_VH + vrow * STR + vs) = vh;
        *(uint4*)(bufc + OFF_VL + vrow * STR + vs) = vl;
        // P compute + quantize
        uint32_t wh[2], wl[2];
        float lacc = 0.0f;
#pragma unroll
        for (int g2 = 0; g2 < 2; g2++) {
            uint32_t uh = 0, ul = 0;
#pragma unroll
            for (int e = 0; e < 4; e++) {
                int j = j0 + pq + g2 * 4 + e;
                float2 mm = msm[j];
                float s = fmaf(sti, mm.x, mm.y) * rlut[abs(gi - j)];
                float p = ex2(s - mx);
                lacc += p;
                float ps = p * 255.0f;
                int ph = __float2int_rn(ps);
                float r = ps - (float)ph;
                int pl = __float2int_rn(r * 128.0f);
                uh |= ((uint32_t)ph & 0xFF) << (8 * e);
                ul |= ((uint32_t)pl & 0xFF) << (8 * e);
            }
            wh[g2] = uh; wl[g2] = ul;
        }
        lsum += lacc;
        *(uint2*)(bufc + OFF_PH + pi * STR + pq) = make_uint2(wh[0], wh[1]);
        *(uint2*)(bufc + OFF_PL + pi * STR + pq) = make_uint2(wl[0], wl[1]);
    };

    auto mma_chunk = [&](int ct) {
        const uint32_t base = sb + (ct & 1) * BUF;
        uint32_t aPh[2][4], aPl[2][4];
#pragma unroll
        for (int mt = 0; mt < 2; mt++) {
            ldsm_x4(aPh[mt], base + OFF_PH + aoff + mt * 16 * STR);
            ldsm_x4(aPl[mt], base + OFF_PL + aoff + mt * 16 * STR);
        }
#pragma unroll
        for (int nt = 0; nt < 4; nt++) {
            uint32_t bVh[2], bVl[2];
            ldsm_x2(bVh, base + OFF_VH + boff + nt * 8 * STR);
            ldsm_x2(bVl, base + OFF_VL + boff + nt * 8 * STR);
#pragma unroll
            for (int mt = 0; mt < 2; mt++) {
                imma_u8s8(S1[mt][nt], aPh[mt], bVh);
                imma_u8s8(S23[mt][nt], aPh[mt], bVl);
                imma_s8s8(S23[mt][nt], aPl[mt], bVh);
            }
        }
    };

    produce(0);
    __syncthreads();
    for (int t = 0; t < L / 32; t++) {
        mma_chunk(t);
        if (t < L / 32 - 1) produce(t + 1);
        __syncthreads();
    }

    // row sums -> 1/l
    lsum += __shfl_xor_sync(0xffffffffu, lsum, 1);
    lsum += __shfl_xor_sync(0xffffffffu, lsum, 2);
    if ((tid & 3) == 0) ls[pi] = lsum;
    __syncthreads();
    if (tid < 64) linv[tid] = 1.0f / ls[tid];
    __syncthreads();

    // epilogue: combine fixed-point accs, normalize, store
    const float c1 = 1.0f / (255.0f * 16.0f);
#pragma unroll
    for (int mt = 0; mt < 2; mt++) {
#pragma unroll
        for (int e2 = 0; e2 < 2; e2++) {
            const int row = wm * 32 + mt * 16 + (lane >> 2) + 8 * e2;
            const float sc = c1 * linv[row];
            float* orow = out + ((size_t)(b * L + i0 + row)) * H + h0;
#pragma unroll
            for (int nt = 0; nt < 4; nt++) {
                int col = wn * 32 + nt * 8 + 2 * (lane & 3);
                float o0 = fmaf((float)S23[mt][nt][2 * e2], 0.0078125f,
                                (float)S1[mt][nt][2 * e2]) * sc;
                float o1 = fmaf((float)S23[mt][nt][2 * e2 + 1], 0.0078125f,
                                (float)S1[mt][nt][2 * e2 + 1]) * sc;
                *(float2*)&orow[col] = make_float2(o0, o1);
            }
        }
    }
}

// ---------------------------------------------------------------------------
// Launch. Input order: opinion_features, text_features, pos_ids,
// Wt, bt, Wo, wa, ba. Output: (B, L, H) float32.
// ---------------------------------------------------------------------------
extern "C" void kernel_launch(void* const* d_in, const int* in_sizes, int n_in,
                              void* d_out, int out_size) {
    const float* opin = (const float*)d_in[0];
    const float* text = (const float*)d_in[1];
    const int*   pos  = (const int*)d_in[2];
    const float* Wt   = (const float*)d_in[3];
    const float* bt   = (const float*)d_in[4];
    const float* Wo   = (const float*)d_in[5];
    const float* wa   = (const float*)d_in[6];
    const float* ba   = (const float*)d_in[7];
    float* out = (float*)d_out;

    static bool attr_done = false;
    if (!attr_done) {
        cudaFuncSetAttribute(k_proj, cudaFuncAttributeMaxDynamicSharedMemorySize,
                             PROJ_SMEM);
        cudaFuncSetAttribute(k_pv, cudaFuncAttributeMaxDynamicSharedMemorySize,
                             PV_SMEM);
        attr_done = true;
    }

    k_vt<<<dim3(L / 64, H / 32, B), 256>>>(opin);
    k_proj<<<dim3(BL / 64, 2), 256, PROJ_SMEM>>>(text, opin, Wt, bt, Wo, wa);
    k_max<<<B * (L / 64), 256>>>(pos, ba);
    k_pv<<<B * (L / 64) * 2, 256, PV_SMEM>>>(pos, ba, out);
}

// round 13
// speedup vs baseline: 1.5157x; 1.5157x over previous
#include <cuda_runtime.h>
#include <cuda_fp16.h>
#include <cstdint>
#include <math.h>

// Problem constants
constexpr int B  = 8;
constexpr int L  = 2048;
constexpr int H  = 256;
constexpr int BL = B * L;
constexpr float L2E = 1.4426950408889634f;
constexpr int PAD = 40;   // halfs per smem tile row (80B) -> conflict-free frags

// Scratch (device globals; no allocation allowed)
__device__ float g_st[BL];           // tanh(text@Wt^T+bt)@wa[:H]
__device__ float g_so[BL];           // tanh(opinion@Wo^T)@wa[H:]
__device__ float g_mx[BL];           // exact row max of L2E-scaled scores
__device__ __half g_VTh[B * H * L];  // V^T fp16 hi: [b][h][j] (8 MB)
__device__ __half g_VTl[B * H * L];  // V^T fp16 lo (residual): [b][h][j] (8 MB)

// ---- fp16 hi/lo split helpers ----
__device__ __forceinline__ void f16_split(float x, unsigned short& h,
                                          unsigned short& l) {
    __half hb = __float2half_rn(x);
    float hf = __half2float(hb);
    __half lb = __float2half_rn(x - hf);
    h = __half_as_ushort(hb);
    l = __half_as_ushort(lb);
}
__device__ __forceinline__ uint32_t pack2(unsigned short lo, unsigned short hi) {
    return (uint32_t)lo | ((uint32_t)hi << 16);
}
__device__ __forceinline__ float ex2(float x) {
    float r;
    asm("ex2.approx.f32 %0, %1;" : "=f"(r) : "f"(x));
    return r;
}
__device__ __forceinline__ uint32_t smem_u32(const void* p) {
    uint32_t a;
    asm("{ .reg .u64 t; cvta.to.shared.u64 t, %1; cvt.u32.u64 %0, t; }"
        : "=r"(a) : "l"(p));
    return a;
}

// ---- warp MMAs: fp16 inputs ----
// main: f32 accumulator
__device__ __forceinline__ void mma_f32(float* c, const uint32_t* a,
                                        uint32_t b0, uint32_t b1) {
    asm volatile(
        "mma.sync.aligned.m16n8k16.row.col.f32.f16.f16.f32 "
        "{%0,%1,%2,%3}, {%4,%5,%6,%7}, {%8,%9}, {%0,%1,%2,%3};"
        : "+f"(c[0]), "+f"(c[1]), "+f"(c[2]), "+f"(c[3])
        : "r"(a[0]), "r"(a[1]), "r"(a[2]), "r"(a[3]), "r"(b0), "r"(b1));
}
// corrections: f16 accumulator (2 x f16x2 regs), potentially double-rate
__device__ __forceinline__ void mma_f16(uint32_t* c, const uint32_t* a,
                                        uint32_t b0, uint32_t b1) {
    asm volatile(
        "mma.sync.aligned.m16n8k16.row.col.f16.f16.f16.f16 "
        "{%0,%1}, {%2,%3,%4,%5}, {%6,%7}, {%0,%1};"
        : "+r"(c[0]), "+r"(c[1])
        : "r"(a[0]), "r"(a[1]), "r"(a[2]), "r"(a[3]), "r"(b0), "r"(b1));
}
__device__ __forceinline__ void ldsm_x4(uint32_t* r, uint32_t addr) {
    asm volatile("ldmatrix.sync.aligned.m8n8.x4.shared.b16 {%0,%1,%2,%3}, [%4];"
                 : "=r"(r[0]), "=r"(r[1]), "=r"(r[2]), "=r"(r[3])
                 : "r"(addr));
}

// ---------------------------------------------------------------------------
// Kernel VT: transpose + fp16-split opinion_features -> g_VTh/g_VTl [b][h][j]
// ---------------------------------------------------------------------------
__global__ __launch_bounds__(256)
void k_vt(const float* __restrict__ opin) {
    __shared__ float tile[64][33];
    const int b = blockIdx.z;
    const int j0 = blockIdx.x * 64;
    const int h0 = blockIdx.y * 32;
    const int tid = threadIdx.x;

#pragma unroll
    for (int it = tid; it < 512; it += 256) {
        int j = it >> 3, hq = (it & 7) * 4;
        float4 v = *(const float4*)&opin[((size_t)(b * L + j0 + j)) * H + h0 + hq];
        tile[j][hq + 0] = v.x; tile[j][hq + 1] = v.y;
        tile[j][hq + 2] = v.z; tile[j][hq + 3] = v.w;
    }
    __syncthreads();

    const int h = tid >> 3, jq = (tid & 7) * 8;
    uint32_t uh[4], ul[4];
#pragma unroll
    for (int k = 0; k < 8; k += 2) {
        unsigned short h0s, l0s, h1s, l1s;
        f16_split(tile[jq + k][h], h0s, l0s);
        f16_split(tile[jq + k + 1][h], h1s, l1s);
        uh[k / 2] = pack2(h0s, h1s);
        ul[k / 2] = pack2(l0s, l1s);
    }
    const size_t o = ((size_t)(b * H + h0 + h)) * L + j0 + jq;
    *(uint4*)&g_VTh[o] = *(uint4*)uh;
    *(uint4*)&g_VTl[o] = *(uint4*)ul;
}

// ---------------------------------------------------------------------------
// Kernel 1: st / so projections via fp16 tensor cores.
// Main term f32-acc; two correction terms share one f16-acc set.
// CTA: 64 rows x N=256, 8 warps (2m x 4n), warp tile 32x64.
// ---------------------------------------------------------------------------
constexpr uint32_t PROJ_SMEM = (2 * 64 * PAD + 2 * 256 * PAD) * 2 + 64 * 4;

__global__ __launch_bounds__(256, 2)
void k_proj(const float* __restrict__ text, const float* __restrict__ opin,
            const float* __restrict__ Wt, const float* __restrict__ bt,
            const float* __restrict__ Wo, const float* __restrict__ wa) {
    extern __shared__ char smraw[];
    unsigned short* Xh = (unsigned short*)smraw;
    unsigned short* Xl = Xh + 64 * PAD;
    unsigned short* Wh = Xl + 64 * PAD;
    unsigned short* Wl = Wh + 256 * PAD;
    float* stp = (float*)(Wl + 256 * PAD);

    const bool isT = (blockIdx.y == 0);
    const float* X = isT ? text : opin;
    const float* W = isT ? Wt : Wo;
    const int row0 = blockIdx.x * 64;
    const int tid = threadIdx.x;
    const int warp = tid >> 5, lane = tid & 31;
    const int wm = warp & 1, wn = warp >> 1;
    const int g = lane >> 2, c4 = lane & 3;

    float acc[2][8][4];
    uint32_t crr[2][8][2];
#pragma unroll
    for (int mt = 0; mt < 2; mt++)
#pragma unroll
        for (int nt = 0; nt < 8; nt++) {
#pragma unroll
            for (int e = 0; e < 4; e++) acc[mt][nt][e] = 0.0f;
            crr[mt][nt][0] = 0u; crr[mt][nt][1] = 0u;
        }

    const int xi = tid >> 2, xk = (tid & 3) * 8;

    for (int kt = 0; kt < 8; kt++) {
        const int k0 = kt * 32;
        float4 xv0 = *(const float4*)&X[(size_t)(row0 + xi) * H + k0 + xk];
        float4 xv1 = *(const float4*)&X[(size_t)(row0 + xi) * H + k0 + xk + 4];
        float4 wv[8];
#pragma unroll
        for (int q = 0; q < 8; q++)
            wv[q] = *(const float4*)&W[(size_t)tid * H + k0 + 4 * q];

        __syncthreads();
        {
            float xf[8] = {xv0.x, xv0.y, xv0.z, xv0.w, xv1.x, xv1.y, xv1.z, xv1.w};
#pragma unroll
            for (int q = 0; q < 8; q += 2) {
                unsigned short h0s, l0s, h1s, l1s;
                f16_split(xf[q], h0s, l0s);
                f16_split(xf[q + 1], h1s, l1s);
                *(uint32_t*)&Xh[xi * PAD + xk + q] = pack2(h0s, h1s);
                *(uint32_t*)&Xl[xi * PAD + xk + q] = pack2(l0s, l1s);
            }
        }
#pragma unroll
        for (int q = 0; q < 8; q++) {
            float wf[4] = {wv[q].x, wv[q].y, wv[q].z, wv[q].w};
#pragma unroll
            for (int e = 0; e < 4; e += 2) {
                unsigned short h0s, l0s, h1s, l1s;
                f16_split(wf[e], h0s, l0s);
                f16_split(wf[e + 1], h1s, l1s);
                *(uint32_t*)&Wh[tid * PAD + 4 * q + e] = pack2(h0s, h1s);
                *(uint32_t*)&Wl[tid * PAD + 4 * q + e] = pack2(l0s, l1s);
            }
        }
        __syncthreads();

#pragma unroll
        for (int ks = 0; ks < 2; ks++) {
            const int kb = ks * 16;
            uint32_t aH[2][4], aL[2][4];
#pragma unroll
            for (int mt = 0; mt < 2; mt++) {
                int base = (wm * 32 + mt * 16 + g) * PAD + kb + 2 * c4;
                aH[mt][0] = *(uint32_t*)&Xh[base];
                aH[mt][1] = *(uint32_t*)&Xh[base + 8 * PAD];
                aH[mt][2] = *(uint32_t*)&Xh[base + 8];
                aH[mt][3] = *(uint32_t*)&Xh[base + 8 * PAD + 8];
                aL[mt][0] = *(uint32_t*)&Xl[base];
                aL[mt][1] = *(uint32_t*)&Xl[base + 8 * PAD];
                aL[mt][2] = *(uint32_t*)&Xl[base + 8];
                aL[mt][3] = *(uint32_t*)&Xl[base + 8 * PAD + 8];
            }
#pragma unroll
            for (int nt = 0; nt < 8; nt++) {
                int bb = (wn * 64 + nt * 8 + g) * PAD + kb + 2 * c4;
                uint32_t bH0 = *(uint32_t*)&Wh[bb], bH1 = *(uint32_t*)&Wh[bb + 8];
                uint32_t bL0 = *(uint32_t*)&Wl[bb], bL1 = *(uint32_t*)&Wl[bb + 8];
#pragma unroll
                for (int mt = 0; mt < 2; mt++) {
                    mma_f32(acc[mt][nt], aH[mt], bH0, bH1);
                    mma_f16(crr[mt][nt], aH[mt], bL0, bL1);
                    mma_f16(crr[mt][nt], aL[mt], bH0, bH1);
                }
            }
        }
    }

    if (tid < 64) stp[tid] = 0.0f;
    __syncthreads();
    const int wo = isT ? 0 : H;
#pragma unroll
    for (int mt = 0; mt < 2; mt++) {
#pragma unroll
        for (int hr = 0; hr < 2; hr++) {
            float s = 0.0f;
#pragma unroll
            for (int nt = 0; nt < 8; nt++) {
                float2 cf = __half22float2(*(__half2*)&crr[mt][nt][hr]);
                float ce[2] = {cf.x, cf.y};
#pragma unroll
                for (int e = 0; e < 2; e++) {
                    int col = wn * 64 + nt * 8 + 2 * c4 + e;
                    float tv = acc[mt][nt][hr * 2 + e] + ce[e];
                    if (isT) tv += bt[col];
                    s += tanhf(tv) * wa[wo + col];
                }
            }
            s += __shfl_xor_sync(0xffffffffu, s, 1);
            s += __shfl_xor_sync(0xffffffffu, s, 2);
            if (c4 == 0)
                atomicAdd(&stp[wm * 32 + mt * 16 + hr * 8 + g], s);
        }
    }
    __syncthreads();
    if (tid < 64) {
        float* dst = isT ? g_st : g_so;
        dst[row0 + tid] = stp[tid];
    }
}

// ---------------------------------------------------------------------------
// Kernel 2: exact per-row max of L2E-scaled scores. MUST use identical fp
// arithmetic to k_pv's producer so p = exp2(s - mx) <= 1 exactly (fp16-safe).
// CTA: 64 rows, 4 threads/row x 512 j each.
// ---------------------------------------------------------------------------
__global__ __launch_bounds__(256)
void k_max(const int* __restrict__ pos, const float* __restrict__ ba) {
    __shared__ float2 msm[L];
    __shared__ float rlut[L];
    const int b = blockIdx.x >> 5;
    const int i0 = (blockIdx.x & 31) * 64;
    const int tid = threadIdx.x;

    for (int j = tid; j < L; j += 256) {
        int p = pos[b * L + j];
        bool op = (p >= 19 && p <= 21) || (p >= 33 && p <= 35) ||
                  (p >= 41 && p <= 46);
        float mu = op ? 8.0f : 1.0f;
        msm[j] = make_float2(mu, g_so[b * L + j] * mu);
    }
    for (int d = tid; d < L; d += 256)
        rlut[d] = ((d == 0) ? 0.5f : 1.0f / log2f(2.0f + (float)d)) * L2E;
    __syncthreads();

    const int ri = tid >> 2, seg = tid & 3;
    const int gi = i0 + ri;
    const float sti = g_st[b * L + gi] + ba[0];

    float m = -1e30f;
    for (int jj = 0; jj < 512; jj++) {
        int j = seg * 512 + jj;
        float2 mm = msm[j];
        float s = fmaf(sti, mm.x, mm.y) * rlut[abs(gi - j)];
        m = fmaxf(m, s);
    }
    m = fmaxf(m, __shfl_xor_sync(0xffffffffu, m, 1));
    m = fmaxf(m, __shfl_xor_sync(0xffffffffu, m, 2));
    if (seg == 0) g_mx[b * L + gi] = m;
}

// ---------------------------------------------------------------------------
// Kernel 3: fused PV + softmax-normalization via fp16 mma.sync.
// Main PhVh f32-acc; corrections PhVl + PlVh share one f16-acc set.
// p = exp2(s - mx) in (0,1] (exact row max from k_max) -> fp16-safe.
// CTA: 128 i-rows x 128 h-cols; full j range per CTA so l is a by-product.
// Double-buffered smem, ldmatrix frags, one barrier per 32-j chunk.
// ---------------------------------------------------------------------------
constexpr uint32_t TILE_B   = 128 * PAD * 2;   // 10240
constexpr uint32_t OFF_PH   = 0;
constexpr uint32_t OFF_PL   = TILE_B;
constexpr uint32_t OFF_VH   = 2 * TILE_B;
constexpr uint32_t OFF_VL   = 3 * TILE_B;
constexpr uint32_t BUF_SZ   = 4 * TILE_B;      // 40960
constexpr uint32_t OFF_MSM  = 2 * BUF_SZ;      // 81920: float2[2048]
constexpr uint32_t OFF_RL   = OFF_MSM + 16384; // 98304: float[2048]
constexpr uint32_t OFF_STI  = OFF_RL + 8192;   // 106496: float[128]
constexpr uint32_t OFF_MX   = OFF_STI + 512;   // 107008: float[128]
constexpr uint32_t OFF_LS   = OFF_MX + 512;    // 107520: float[256]
constexpr uint32_t OFF_LINV = OFF_LS + 1024;   // 108544: float[128]
constexpr uint32_t PV_SMEM  = OFF_LINV + 512;  // 109056

__global__ __launch_bounds__(256, 2)
void k_pv(const int* __restrict__ pos, const float* __restrict__ ba,
          float* __restrict__ out) {
    extern __shared__ char smraw[];
    char* smc = smraw;
    const uint32_t sb = smem_u32(smraw);

    float2* msm  = (float2*)(smc + OFF_MSM);
    float*  rlut = (float*)(smc + OFF_RL);
    float*  stis = (float*)(smc + OFF_STI);
    float*  mxs  = (float*)(smc + OFF_MX);
    float*  ls   = (float*)(smc + OFF_LS);
    float*  linv = (float*)(smc + OFF_LINV);

    const int cta = blockIdx.x;
    const int b = cta >> 5;
    const int i0 = ((cta & 31) >> 1) * 128;
    const int h0 = (cta & 1) * 128;
    const int tid = threadIdx.x;
    const int warp = tid >> 5, lane = tid & 31;
    const int wm = warp >> 1, wn = warp & 1;   // 4m x 2n
    const int g = lane >> 2, c4 = lane & 3;

    // prologue: per-batch j-tables + per-row st / mx
    for (int j = tid; j < L; j += 256) {
        int p = pos[b * L + j];
        bool op = (p >= 19 && p <= 21) || (p >= 33 && p <= 35) ||
                  (p >= 41 && p <= 46);
        float mu = op ? 8.0f : 1.0f;
        float so = g_so[b * L + j];
        msm[j] = make_float2(mu, so * mu);
    }
    for (int d = tid; d < L; d += 256)
        rlut[d] = ((d == 0) ? 0.5f : 1.0f / log2f(2.0f + (float)d)) * L2E;
    if (tid < 128) {
        stis[tid] = g_st[b * L + i0 + tid] + ba[0];
        mxs[tid]  = g_mx[b * L + i0 + tid];
    }
    __syncthreads();

    // producer thread mapping: row pi (both P-row i and V-row h), 16 j's
    const int pi = tid >> 1, pk0 = (tid & 1) * 16;
    const int gi = i0 + pi;
    const float sti = stis[pi];
    const float mx = mxs[pi];
    const __half* vhp = &g_VTh[(size_t)(b * H + h0 + pi) * L + pk0];
    const __half* vlp = &g_VTl[(size_t)(b * H + h0 + pi) * L + pk0];
    float lsum = 0.0f;

    // ldmatrix lane-invariant offsets (bytes)
    const uint32_t aoff =
        ((lane & 15) * PAD + (lane >> 4) * 8) * 2 + (wm * 32) * PAD * 2;
    const uint32_t boff =
        (((lane & 7) + ((lane >> 4) & 1) * 8) * PAD + ((lane >> 3) & 1) * 8) * 2 +
        (wn * 64) * PAD * 2;

    float acc[2][8][4];
    uint32_t crr[2][8][2];
#pragma unroll
    for (int mt = 0; mt < 2; mt++)
#pragma unroll
        for (int nt = 0; nt < 8; nt++) {
#pragma unroll
            for (int e = 0; e < 4; e++) acc[mt][nt][e] = 0.0f;
            crr[mt][nt][0] = 0u; crr[mt][nt][1] = 0u;
        }

    auto produceP = [&](int ct) {
        char* bufc = smc + (ct & 1) * BUF_SZ;
        const int j0n = ct * 32;
        uint32_t hp[8], lp[8];
        float lacc = 0.0f;
#pragma unroll
        for (int q = 0; q < 16; q += 2) {
            int j = j0n + pk0 + q;
            float2 m0 = msm[j], m1 = msm[j + 1];
            float s0 = fmaf(sti, m0.x, m0.y) * rlut[abs(gi - j)];
            float s1 = fmaf(sti, m1.x, m1.y) * rlut[abs(gi - j - 1)];
            float p0 = ex2(s0 - mx), p1 = ex2(s1 - mx);
            lacc += p0 + p1;
            unsigned short h0s, l0s, h1s, l1s;
            f16_split(p0, h0s, l0s);
            f16_split(p1, h1s, l1s);
            hp[q / 2] = pack2(h0s, h1s);
            lp[q / 2] = pack2(l0s, l1s);
        }
        lsum += lacc;
        uint32_t off = (pi * PAD + pk0) * 2;
        *(uint4*)(bufc + OFF_PH + off) = *(uint4*)&hp[0];
        *(uint4*)(bufc + OFF_PH + off + 16) = *(uint4*)&hp[4];
        *(uint4*)(bufc + OFF_PL + off) = *(uint4*)&lp[0];
        *(uint4*)(bufc + OFF_PL + off + 16) = *(uint4*)&lp[4];
    };
    auto storeV = [&](int ct, uint4 vh0, uint4 vh1, uint4 vl0, uint4 vl1) {
        char* bufc = smc + (ct & 1) * BUF_SZ;
        uint32_t off = (pi * PAD + pk0) * 2;
        *(uint4*)(bufc + OFF_VH + off) = vh0;
        *(uint4*)(bufc + OFF_VH + off + 16) = vh1;
        *(uint4*)(bufc + OFF_VL + off) = vl0;
        *(uint4*)(bufc + OFF_VL + off + 16) = vl1;
    };
    auto mma_ks = [&](int tb, int ks) {
        uint32_t base = sb + tb * BUF_SZ + ks * 32;
        uint32_t aH[2][4], aL[2][4];
#pragma unroll
        for (int mt = 0; mt < 2; mt++) {
            ldsm_x4(aH[mt], base + OFF_PH + aoff + mt * (16 * PAD * 2));
            ldsm_x4(aL[mt], base + OFF_PL + aoff + mt * (16 * PAD * 2));
        }
#pragma unroll
        for (int ntp = 0; ntp < 4; ntp++) {
            uint32_t bh[4], bl[4];
            ldsm_x4(bh, base + OFF_VH + boff + ntp * (16 * PAD * 2));
            ldsm_x4(bl, base + OFF_VL + boff + ntp * (16 * PAD * 2));
#pragma unroll
            for (int s2 = 0; s2 < 2; s2++) {
                const int nt = ntp * 2 + s2;
#pragma unroll
                for (int mt = 0; mt < 2; mt++) {
                    mma_f32(acc[mt][nt], aH[mt], bh[2 * s2], bh[2 * s2 + 1]);
                    mma_f16(crr[mt][nt], aH[mt], bl[2 * s2], bl[2 * s2 + 1]);
                    mma_f16(crr[mt][nt], aL[mt], bh[2 * s2], bh[2 * s2 + 1]);
                }
            }
        }
    };

    // produce chunk 0
    {
        uint4 vh0 = *(const uint4*)(vhp);
        uint4 vh1 = *(const uint4*)(vhp + 8);
        uint4 vl0 = *(const uint4*)(vlp);
        uint4 vl1 = *(const uint4*)(vlp + 8);
        storeV(0, vh0, vh1, vl0, vl1);
        produceP(0);
    }
    __syncthreads();

    for (int t = 0; t < L / 32; t++) {
        uint4 vh0, vh1, vl0, vl1;
        const bool more = (t < L / 32 - 1);
        if (more) {
            const __half* ph = vhp + (t + 1) * 32;
            const __half* pl = vlp + (t + 1) * 32;
            vh0 = *(const uint4*)(ph);
            vh1 = *(const uint4*)(ph + 8);
            vl0 = *(const uint4*)(pl);
            vl1 = *(const uint4*)(pl + 8);
        }
        mma_ks(t & 1, 0);
        if (more) {
            storeV(t + 1, vh0, vh1, vl0, vl1);
            produceP(t + 1);
        }
        mma_ks(t & 1, 1);
        __syncthreads();
    }

    // row-sum reduction -> 1/l
    ls[tid] = lsum;
    __syncthreads();
    if (tid < 128) linv[tid] = 1.0f / (ls[2 * tid] + ls[2 * tid + 1]);
    __syncthreads();

    // write output: (main + correction) scaled by 1/l
#pragma unroll
    for (int mt = 0; mt < 2; mt++) {
        const int r0l = wm * 32 + mt * 16 + g;
        const float il0 = linv[r0l], il1 = linv[r0l + 8];
#pragma unroll
        for (int nt = 0; nt < 8; nt++) {
            int col = h0 + wn * 64 + nt * 8 + 2 * c4;
            float2 c0 = __half22float2(*(__half2*)&crr[mt][nt][0]);
            float2 c1 = __half22float2(*(__half2*)&crr[mt][nt][1]);
            float2 v0 = make_float2((acc[mt][nt][0] + c0.x) * il0,
                                    (acc[mt][nt][1] + c0.y) * il0);
            float2 v1 = make_float2((acc[mt][nt][2] + c1.x) * il1,
                                    (acc[mt][nt][3] + c1.y) * il1);
            *(float2*)&out[((size_t)(b * L + i0 + r0l)) * H + col] = v0;
            *(float2*)&out[((size_t)(b * L + i0 + r0l + 8)) * H + col] = v1;
        }
    }
}

// ---------------------------------------------------------------------------
// Launch. Input order: opinion_features, text_features, pos_ids,
// Wt, bt, Wo, wa, ba. Output: (B, L, H) float32.
// ---------------------------------------------------------------------------
extern "C" void kernel_launch(void* const* d_in, const int* in_sizes, int n_in,
                              void* d_out, int out_size) {
    const float* opin = (const float*)d_in[0];
    const float* text = (const float*)d_in[1];
    const int*   pos  = (const int*)d_in[2];
    const float* Wt   = (const float*)d_in[3];
    const float* bt   = (const float*)d_in[4];
    const float* Wo   = (const float*)d_in[5];
    const float* wa   = (const float*)d_in[6];
    const float* ba   = (const float*)d_in[7];
    float* out = (float*)d_out;

    static bool attr_done = false;
    if (!attr_done) {
        cudaFuncSetAttribute(k_proj, cudaFuncAttributeMaxDynamicSharedMemorySize,
                             PROJ_SMEM);
        cudaFuncSetAttribute(k_pv, cudaFuncAttributeMaxDynamicSharedMemorySize,
                             PV_SMEM);
        attr_done = true;
    }

    k_vt<<<dim3(L / 64, H / 32, B), 256>>>(opin);
    k_proj<<<dim3(BL / 64, 2), 256, PROJ_SMEM>>>(text, opin, Wt, bt, Wo, wa);
    k_max<<<B * (L / 64), 256>>>(pos, ba);
    k_pv<<<B * (L / 64), 256, PV_SMEM>>>(pos, ba, out);
}